// round 16
// baseline (speedup 1.0000x reference)
#include <cuda_runtime.h>
#include <cuda_bf16.h>
#include <cuda_fp16.h>
#include <cstdint>

#define BATCH  4
#define SEQ    4096
#define DMODEL 1024

// GEMM: CTA 128x256, 256 threads (8 warps as 2x4), warp tile 64x64.
// K in chunks of 32; pre-split 16-bit operands in gmem; cp.async pipeline.
// Stage layout/plane-count/stage-depth templated on TERMS:
//   TERMS=3 (bf16 3-term): Ah,Al,Bh,Bl planes, 61440B/stage, 3 stages (R12-identical)
//   TERMS=1 (fp16 1-term): Ah,Bh planes,       30720B/stage, 6 stages (deep pipeline)
#define BM 128
#define BN 256
#define THREADS 256
#define ROW_B   80
#define A_HALF  (128 * ROW_B)       // 10240
#define B_HALF  (256 * ROW_B)       // 20480
#define SMEM_DYN 184320             // = 3*(2A+2B) = 6*(A+B)

// ---------------------------------------------------------------------------
// Scratch (device globals; allocation forbidden)
// ---------------------------------------------------------------------------
#define SD ((size_t)BATCH * SEQ * DMODEL)
#define SS ((size_t)BATCH * SEQ * SEQ)
__device__ uint16_t g_xqh[SD], g_xql[SD];
__device__ uint16_t g_xvh[SD], g_xvl[SD];
__device__ uint16_t g_wqh[DMODEL*DMODEL], g_wql[DMODEL*DMODEL];
__device__ uint16_t g_wvh[DMODEL*DMODEL], g_wvl[DMODEL*DMODEL];
__device__ uint16_t g_Qh[SD], g_Ql[SD];
__device__ uint16_t g_Vh[SD], g_Vl[SD];
__device__ uint16_t g_Vth[SD];
__device__ float    g_S[SS];
__device__ uint16_t g_Ph[SS];

// ---------------------------------------------------------------------------
// helpers
// ---------------------------------------------------------------------------
__device__ __forceinline__ uint32_t smem_u32(const void* p) {
    uint32_t a;
    asm("{ .reg .u64 t; cvta.to.shared.u64 t, %1; cvt.u32.u64 %0, t; }" : "=r"(a) : "l"(p));
    return a;
}
__device__ __forceinline__ void cpasync16(uint32_t dst, const void* src) {
    asm volatile("{ .reg .u64 g; cvta.to.global.u64 g, %1; "
                 "cp.async.cg.shared.global [%0], [g], 16; }"
                 :: "r"(dst), "l"(src) : "memory");
}
#define CP_COMMIT() asm volatile("cp.async.commit_group;" ::: "memory")
#define CP_WAIT(n)  asm volatile("cp.async.wait_group %0;" :: "n"(n) : "memory")

#define LDSM4(d, addr) \
    asm volatile("ldmatrix.sync.aligned.m8n8.x4.shared.b16 {%0,%1,%2,%3}, [%4];" \
        : "=r"((d)[0]), "=r"((d)[1]), "=r"((d)[2]), "=r"((d)[3]) : "r"(addr))

template<int FP16>
__device__ __forceinline__ void mma16(float* d, const uint32_t* a,
                                      uint32_t b0, uint32_t b1v) {
    if constexpr (FP16) {
        asm volatile("mma.sync.aligned.m16n8k16.row.col.f32.f16.f16.f32 "
            "{%0,%1,%2,%3}, {%4,%5,%6,%7}, {%8,%9}, {%0,%1,%2,%3};"
            : "+f"(d[0]), "+f"(d[1]), "+f"(d[2]), "+f"(d[3])
            : "r"(a[0]), "r"(a[1]), "r"(a[2]), "r"(a[3]), "r"(b0), "r"(b1v));
    } else {
        asm volatile("mma.sync.aligned.m16n8k16.row.col.f32.bf16.bf16.f32 "
            "{%0,%1,%2,%3}, {%4,%5,%6,%7}, {%8,%9}, {%0,%1,%2,%3};"
            : "+f"(d[0]), "+f"(d[1]), "+f"(d[2]), "+f"(d[3])
            : "r"(a[0]), "r"(a[1]), "r"(a[2]), "r"(a[3]), "r"(b0), "r"(b1v));
    }
}

__device__ __forceinline__ void split2(float x, float y, uint32_t& hi, uint32_t& lo) {
    __nv_bfloat16 hx = __float2bfloat16(x), hy = __float2bfloat16(y);
    __nv_bfloat162 hp(hx, hy);
    hi = *reinterpret_cast<uint32_t*>(&hp);
    __nv_bfloat162 lp = __floats2bfloat162_rn(x - __bfloat162float(hx),
                                              y - __bfloat162float(hy));
    lo = *reinterpret_cast<uint32_t*>(&lp);
}

// ---------------------------------------------------------------------------
// 16-bit split NT GEMM:  C = scale * A·B^T (+ b1 + b2)
// TERMS=3: Ah*Bh + Ah*Bl + Al*Bh (bf16, 3 stages) ; TERMS=1: Ah*Bh (fp16, 6 stages)
// MODE bit0: fp32 C ; bit1: bf16 split Ch/Cl
// ---------------------------------------------------------------------------
template<int TERMS, int FP16, int MODE>
__global__ __launch_bounds__(THREADS, 1)
void gemm_nt(const uint16_t* __restrict__ Ah, const uint16_t* __restrict__ Al,
             const uint16_t* __restrict__ Bh, const uint16_t* __restrict__ Bl,
             float* __restrict__ C, uint16_t* __restrict__ Ch, uint16_t* __restrict__ Cl,
             int K, int ldc,
             const float* __restrict__ b1, const float* __restrict__ b2,
             float scale)
{
    constexpr int APL = (TERMS == 3) ? 2 : 1;
    constexpr int BPL = (TERMS >= 2) ? 2 : 1;
    constexpr uint32_t OFFAL = A_HALF;                 // valid only if APL==2
    constexpr uint32_t OFFBH = (uint32_t)APL * A_HALF;
    constexpr uint32_t OFFBL = OFFBH + B_HALF;         // valid only if BPL==2
    constexpr uint32_t STAGEB = (uint32_t)(APL * A_HALF + BPL * B_HALF);
    constexpr int NST = (TERMS == 3) ? 3 : 6;

    extern __shared__ char smem[];
    const uint32_t sbase = smem_u32(smem);
    const int tid = threadIdx.x, lane = tid & 31, w = tid >> 5;
    const int wm = w & 1, wn = w >> 1;

    const int m0 = blockIdx.y * BM;
    const int n0 = blockIdx.x * BN;

    const uint32_t offA = (uint32_t)((wm * 64 + ((lane >> 3) & 1) * 8 + (lane & 7)) * ROW_B
                                     + ((lane >> 4) & 1) * 16);
    const uint32_t offB = (uint32_t)((wn * 64 + ((lane >> 4) & 1) * 8 + (lane & 7)) * ROW_B
                                     + ((lane >> 3) & 1) * 16);

    float acc[4][8][4];
    #pragma unroll
    for (int i = 0; i < 4; ++i)
        #pragma unroll
        for (int j = 0; j < 8; ++j)
            #pragma unroll
            for (int q = 0; q < 4; ++q) acc[i][j][q] = 0.f;

    const int nc = K >> 5;

    auto issue = [&](int c, int s) {
        const uint32_t sb = sbase + (uint32_t)s * STAGEB;
        const int k0 = c * 32;
        #pragma unroll
        for (int i = 0; i < 2; ++i) {
            int idx = tid + i * 256;
            int row = idx >> 2, cc = idx & 3;
            const uint32_t d = sb + row * ROW_B + cc * 16;
            const long long g = (long long)(m0 + row) * K + k0 + cc * 8;
            cpasync16(d, Ah + g);
            if (TERMS == 3) cpasync16(d + OFFAL, Al + g);
        }
        #pragma unroll
        for (int i = 0; i < 4; ++i) {
            int idx = tid + i * 256;
            int row = idx >> 2, cc = idx & 3;
            const uint32_t d = sb + row * ROW_B + cc * 16;
            const long long g = (long long)(n0 + row) * K + k0 + cc * 8;
            cpasync16(d + OFFBH, Bh + g);
            if (TERMS >= 2) cpasync16(d + OFFBL, Bl + g);
        }
    };

    // prologue: NST-1 stages in flight (nc >= NST-1 always holds here)
    #pragma unroll
    for (int s = 0; s < NST - 1; ++s) { issue(s, s); CP_COMMIT(); }

    int st = 0;
    for (int c = 0; c < nc; ++c) {
        const int rem = nc - c - 1;     // groups that will still complete after c
        if constexpr (NST == 3) {
            if (rem >= 1) { CP_WAIT(1); } else { CP_WAIT(0); }
        } else {
            if      (rem >= 4) { CP_WAIT(4); }
            else if (rem == 3) { CP_WAIT(3); }
            else if (rem == 2) { CP_WAIT(2); }
            else if (rem == 1) { CP_WAIT(1); }
            else               { CP_WAIT(0); }
        }
        __syncthreads();
        if (c + NST - 1 < nc) {
            int s = c + NST - 1;
            int slot = s % NST;
            issue(s, slot); CP_COMMIT();
        }

        const uint32_t base = sbase + (uint32_t)st * STAGEB;
        #pragma unroll
        for (int kk2 = 0; kk2 < 2; ++kk2) {
            const uint32_t kb = kk2 * 32;
            uint32_t ah[4][4], bhf[4][4];
            #pragma unroll
            for (int mi = 0; mi < 4; ++mi) LDSM4(ah[mi], base + offA + mi * (16 * ROW_B) + kb);
            #pragma unroll
            for (int nt = 0; nt < 4; ++nt) LDSM4(bhf[nt], base + OFFBH + offB + nt * (16 * ROW_B) + kb);
            #pragma unroll
            for (int mi = 0; mi < 4; ++mi)
                #pragma unroll
                for (int nt = 0; nt < 4; ++nt)
                    #pragma unroll
                    for (int nh = 0; nh < 2; ++nh)
                        mma16<FP16>(acc[mi][nt * 2 + nh], ah[mi], bhf[nt][nh * 2], bhf[nt][nh * 2 + 1]);
            if constexpr (TERMS >= 2) {
                uint32_t blf[4][4];
                #pragma unroll
                for (int nt = 0; nt < 4; ++nt) LDSM4(blf[nt], base + OFFBL + offB + nt * (16 * ROW_B) + kb);
                #pragma unroll
                for (int mi = 0; mi < 4; ++mi)
                    #pragma unroll
                    for (int nt = 0; nt < 4; ++nt)
                        #pragma unroll
                        for (int nh = 0; nh < 2; ++nh)
                            mma16<FP16>(acc[mi][nt * 2 + nh], ah[mi], blf[nt][nh * 2], blf[nt][nh * 2 + 1]);
            }
            if constexpr (TERMS == 3) {
                uint32_t alf[4][4];
                #pragma unroll
                for (int mi = 0; mi < 4; ++mi) LDSM4(alf[mi], base + OFFAL + offA + mi * (16 * ROW_B) + kb);
                #pragma unroll
                for (int mi = 0; mi < 4; ++mi)
                    #pragma unroll
                    for (int nt = 0; nt < 4; ++nt)
                        #pragma unroll
                        for (int nh = 0; nh < 2; ++nh)
                            mma16<FP16>(acc[mi][nt * 2 + nh], alf[mi], bhf[nt][nh * 2], bhf[nt][nh * 2 + 1]);
            }
        }

        if (++st == NST) st = 0;
    }

    const int gid = lane >> 2, tig = lane & 3;
    #pragma unroll
    for (int mi = 0; mi < 4; ++mi) {
        const int row = m0 + wm * 64 + mi * 16 + gid;
        #pragma unroll
        for (int ni = 0; ni < 8; ++ni) {
            const int col = n0 + wn * 64 + ni * 8 + tig * 2;
            float bb0 = 0.f, bb1 = 0.f;
            if (b1) { bb0 += b1[col]; bb1 += b1[col + 1]; }
            if (b2) { bb0 += b2[col]; bb1 += b2[col + 1]; }
            float2 o0, o1;
            o0.x = acc[mi][ni][0] * scale + bb0;
            o0.y = acc[mi][ni][1] * scale + bb1;
            o1.x = acc[mi][ni][2] * scale + bb0;
            o1.y = acc[mi][ni][3] * scale + bb1;
            const long long i0 = (long long)row * ldc + col;
            const long long i1 = i0 + 8LL * ldc;
            if constexpr (MODE & 1) {
                *(float2*)(C + i0) = o0;
                *(float2*)(C + i1) = o1;
            }
            if constexpr (MODE & 2) {
                uint32_t h, l;
                split2(o0.x, o0.y, h, l);
                *(uint32_t*)(Ch + i0) = h; *(uint32_t*)(Cl + i0) = l;
                split2(o1.x, o1.y, h, l);
                *(uint32_t*)(Ch + i1) = h; *(uint32_t*)(Cl + i1) = l;
            }
        }
    }
}

// ---------------------------------------------------------------------------
// fp32 -> bf16 hi/lo split
// ---------------------------------------------------------------------------
__global__ __launch_bounds__(256)
void split_f32(const float4* __restrict__ in, uint2* __restrict__ hi,
               uint2* __restrict__ lo, int n4)
{
    int i = blockIdx.x * 256 + threadIdx.x;
    if (i >= n4) return;
    float4 v = in[i];
    uint32_t h0, l0, h1, l1;
    split2(v.x, v.y, h0, l0);
    split2(v.z, v.w, h1, l1);
    hi[i] = make_uint2(h0, h1);
    lo[i] = make_uint2(l0, l1);
}

// ---------------------------------------------------------------------------
// V transpose from bf16 hi/lo planes -> fp16: Vth[b][d][s] = f16(Vh+Vl)
// ---------------------------------------------------------------------------
__global__ __launch_bounds__(256)
void transpose_v16(const uint16_t* __restrict__ Vh, const uint16_t* __restrict__ Vl,
                   uint16_t* __restrict__ Vth)
{
    __shared__ float t[32][33];
    const int b  = blockIdx.z;
    const int s0 = blockIdx.x * 32;
    const int d0 = blockIdx.y * 32;
    const uint16_t* Hh = Vh + (long long)b * SEQ * DMODEL;
    const uint16_t* Hl = Vl + (long long)b * SEQ * DMODEL;
    uint16_t* T = Vth + (long long)b * SEQ * DMODEL;
    const int x = threadIdx.x, y = threadIdx.y;
    #pragma unroll
    for (int i = 0; i < 32; i += 8) {
        const long long g = (long long)(s0 + y + i) * DMODEL + d0 + x;
        __nv_bfloat16 hb = *reinterpret_cast<const __nv_bfloat16*>(Hh + g);
        __nv_bfloat16 lb = *reinterpret_cast<const __nv_bfloat16*>(Hl + g);
        t[y + i][x] = __bfloat162float(hb) + __bfloat162float(lb);
    }
    __syncthreads();
    #pragma unroll
    for (int i = 0; i < 32; i += 8) {
        __half h = __float2half_rn(t[x][y + i]);
        T[(long long)(d0 + y + i) * SEQ + s0 + x] = *reinterpret_cast<uint16_t*>(&h);
    }
}

// ---------------------------------------------------------------------------
// Row softmax: fp32 in, fp16 out
// ---------------------------------------------------------------------------
__global__ __launch_bounds__(512)
void softmax_rows(const float* __restrict__ S, uint16_t* __restrict__ Ph)
{
    const float* p = S + (long long)blockIdx.x * SEQ;
    const int tid = threadIdx.x;

    float4 a = ((const float4*)p)[tid];
    float4 b = ((const float4*)p)[tid + 512];

    __shared__ float sred[16];
    __shared__ float sval;

    float m = fmaxf(fmaxf(fmaxf(a.x, a.y), fmaxf(a.z, a.w)),
                    fmaxf(fmaxf(b.x, b.y), fmaxf(b.z, b.w)));
    #pragma unroll
    for (int o = 16; o > 0; o >>= 1) m = fmaxf(m, __shfl_xor_sync(0xffffffffu, m, o));
    if ((tid & 31) == 0) sred[tid >> 5] = m;
    __syncthreads();
    if (tid < 32) {
        float x = (tid < 16) ? sred[tid] : __int_as_float(0xff800000);
        #pragma unroll
        for (int o = 8; o > 0; o >>= 1) x = fmaxf(x, __shfl_xor_sync(0xffffffffu, x, o));
        if (tid == 0) sval = x;
    }
    __syncthreads();
    const float rmax = sval;
    __syncthreads();

    a.x = expf(a.x - rmax); a.y = expf(a.y - rmax);
    a.z = expf(a.z - rmax); a.w = expf(a.w - rmax);
    b.x = expf(b.x - rmax); b.y = expf(b.y - rmax);
    b.z = expf(b.z - rmax); b.w = expf(b.w - rmax);

    float s = (a.x + a.y) + (a.z + a.w) + (b.x + b.y) + (b.z + b.w);
    #pragma unroll
    for (int o = 16; o > 0; o >>= 1) s += __shfl_xor_sync(0xffffffffu, s, o);
    if ((tid & 31) == 0) sred[tid >> 5] = s;
    __syncthreads();
    if (tid < 32) {
        float x = (tid < 16) ? sred[tid] : 0.f;
        #pragma unroll
        for (int o = 8; o > 0; o >>= 1) x += __shfl_xor_sync(0xffffffffu, x, o);
        if (tid == 0) sval = x;
    }
    __syncthreads();
    const float inv = 1.0f / sval;

    __half2 p0 = __floats2half2_rn(a.x * inv, a.y * inv);
    __half2 p1 = __floats2half2_rn(a.z * inv, a.w * inv);
    __half2 p2 = __floats2half2_rn(b.x * inv, b.y * inv);
    __half2 p3 = __floats2half2_rn(b.z * inv, b.w * inv);

    const long long rb = (long long)blockIdx.x * (SEQ / 4);
    ((uint2*)Ph)[rb + tid]       = make_uint2(*reinterpret_cast<uint32_t*>(&p0),
                                              *reinterpret_cast<uint32_t*>(&p1));
    ((uint2*)Ph)[rb + 512 + tid] = make_uint2(*reinterpret_cast<uint32_t*>(&p2),
                                              *reinterpret_cast<uint32_t*>(&p3));
}

// ---------------------------------------------------------------------------
// Launcher — R15 DAG: transpose off scores critical path; splits parallel.
// ---------------------------------------------------------------------------
extern "C" void kernel_launch(void* const* d_in, const int* in_sizes, int n_in,
                              void* d_out, int out_size)
{
    const float* query = (const float*)d_in[0];
    const float* value = (const float*)d_in[1];
    const float* Wq    = (const float*)d_in[2];
    const float* bq    = (const float*)d_in[3];
    const float* qkb   = (const float*)d_in[4];
    const float* Wv    = (const float*)d_in[5];
    const float* bv    = (const float*)d_in[6];
    float* out = (float*)d_out;

    uint16_t *xqh, *xql, *xvh, *xvl, *wqh, *wql, *wvh, *wvl;
    uint16_t *Qh, *Ql, *Vh, *Vl, *Vth, *Ph;
    float *Sc;
    cudaGetSymbolAddress((void**)&xqh, g_xqh); cudaGetSymbolAddress((void**)&xql, g_xql);
    cudaGetSymbolAddress((void**)&xvh, g_xvh); cudaGetSymbolAddress((void**)&xvl, g_xvl);
    cudaGetSymbolAddress((void**)&wqh, g_wqh); cudaGetSymbolAddress((void**)&wql, g_wql);
    cudaGetSymbolAddress((void**)&wvh, g_wvh); cudaGetSymbolAddress((void**)&wvl, g_wvl);
    cudaGetSymbolAddress((void**)&Qh,  g_Qh);  cudaGetSymbolAddress((void**)&Ql,  g_Ql);
    cudaGetSymbolAddress((void**)&Vh,  g_Vh);  cudaGetSymbolAddress((void**)&Vl,  g_Vl);
    cudaGetSymbolAddress((void**)&Vth, g_Vth);
    cudaGetSymbolAddress((void**)&Sc,  g_S);
    cudaGetSymbolAddress((void**)&Ph,  g_Ph);

    static bool init_done = false;
    static cudaStream_t st[3];
    static cudaEvent_t evPV, evS, evT, evB[3];
    if (!init_done) {
        cudaFuncSetAttribute(gemm_nt<3,0,1>, cudaFuncAttributeMaxDynamicSharedMemorySize, SMEM_DYN);
        cudaFuncSetAttribute(gemm_nt<3,0,2>, cudaFuncAttributeMaxDynamicSharedMemorySize, SMEM_DYN);
        cudaFuncSetAttribute(gemm_nt<1,1,1>, cudaFuncAttributeMaxDynamicSharedMemorySize, SMEM_DYN);
        for (int i = 0; i < 3; ++i) cudaStreamCreateWithFlags(&st[i], cudaStreamNonBlocking);
        cudaEventCreateWithFlags(&evPV, cudaEventDisableTiming);
        cudaEventCreateWithFlags(&evS,  cudaEventDisableTiming);
        cudaEventCreateWithFlags(&evT,  cudaEventDisableTiming);
        for (int i = 0; i < 3; ++i) cudaEventCreateWithFlags(&evB[i], cudaEventDisableTiming);
        init_done = true;
    }

    const int S = SEQ, D = DMODEL, B = BATCH;
    const long long sd = (long long)S * D;
    const long long ss = (long long)S * S;

    // fork st[0] from origin at entry
    cudaEventRecord(evS, 0);
    cudaStreamWaitEvent(st[0], evS, 0);

    // origin: query/Wq splits -> projQ
    split_f32<<<(B*S*D/4 + 255)/256, 256>>>((const float4*)query, (uint2*)xqh, (uint2*)xql, B*S*D/4);
    split_f32<<<(D*D/4 + 255)/256, 256>>>((const float4*)Wq, (uint2*)wqh, (uint2*)wql, D*D/4);
    dim3 gp(D / BN, (B * S) / BM, 1);
    gemm_nt<3,0,2><<<gp, THREADS, SMEM_DYN>>>(xqh, xql, wqh, wql,
                                              nullptr, Qh, Ql, D, D,
                                              bq, qkb, 1.0f);

    // st[0]: value/Wv splits -> projV (Vh/Vl only) -> (evPV) -> transpose -> (evT)
    split_f32<<<(B*S*D/4 + 255)/256, 256, 0, st[0]>>>((const float4*)value, (uint2*)xvh, (uint2*)xvl, B*S*D/4);
    split_f32<<<(D*D/4 + 255)/256, 256, 0, st[0]>>>((const float4*)Wv, (uint2*)wvh, (uint2*)wvl, D*D/4);
    gemm_nt<3,0,2><<<gp, THREADS, SMEM_DYN, st[0]>>>(xvh, xvl, wvh, wvl,
                                                     nullptr, Vh, Vl, D, D,
                                                     bv, nullptr, 1.0f);
    cudaEventRecord(evPV, st[0]);
    transpose_v16<<<dim3(S / 32, D / 32, B), dim3(32, 8), 0, st[0]>>>(Vh, Vl, Vth);
    cudaEventRecord(evT, st[0]);

    // join: scores need projQ (origin order) + projV
    cudaStreamWaitEvent(0, evPV, 0);
    cudaEventRecord(evS, 0);

    // per-batch chains: scores_b -> softmax_b -> PV_b on 4 streams
    dim3 gs(S / BN, S / BM, 1);
    dim3 go(D / BN, S / BM, 1);
    for (int b = 0; b < B; ++b) {
        cudaStream_t sb = (b == 0) ? (cudaStream_t)0 : st[b - 1];
        if (b > 0) cudaStreamWaitEvent(sb, evS, 0);
        gemm_nt<3,0,1><<<gs, THREADS, SMEM_DYN, sb>>>(
            Qh + b * sd, Ql + b * sd, Vh + b * sd, Vl + b * sd,
            Sc + b * ss, nullptr, nullptr, D, S,
            nullptr, nullptr, 0.125f);
        softmax_rows<<<S, 512, 0, sb>>>(Sc + b * ss, Ph + b * ss);
        cudaStreamWaitEvent(sb, evT, 0);     // PV needs Vth
        gemm_nt<1,1,1><<<go, THREADS, SMEM_DYN, sb>>>(
            Ph + b * ss, nullptr, Vth + b * sd, nullptr,
            out + b * sd, nullptr, nullptr, S, D,
            nullptr, nullptr, 1.0f);
        if (b > 0) cudaEventRecord(evB[b - 1], sb);
    }
    for (int i = 0; i < 3; ++i) cudaStreamWaitEvent(0, evB[i], 0);
}

// round 17
// speedup vs baseline: 1.0117x; 1.0117x over previous
#include <cuda_runtime.h>
#include <cuda_bf16.h>
#include <cuda_fp16.h>
#include <cstdint>

#define BATCH  4
#define SEQ    4096
#define DMODEL 1024

// GEMM: CTA 128x256, 256 threads (8 warps as 2x4), warp tile 64x64.
// K in chunks of 32; pre-split 16-bit operands in gmem; cp.async pipeline.
//   TERMS=3 (bf16 3-term): Ah,Al,Bh,Bl planes, 61440B/stage, 3 stages
//   TERMS=1 (fp16 1-term): Ah,Bh planes,       30720B/stage, 6 stages
#define BM 128
#define BN 256
#define THREADS 256
#define ROW_B   80
#define A_HALF  (128 * ROW_B)       // 10240
#define B_HALF  (256 * ROW_B)       // 20480
#define SMEM_DYN 184320             // = 3*(2A+2B) = 6*(A+B)

// ---------------------------------------------------------------------------
// Scratch (device globals; allocation forbidden)
// ---------------------------------------------------------------------------
#define SD ((size_t)BATCH * SEQ * DMODEL)
#define SS ((size_t)BATCH * SEQ * SEQ)
__device__ uint16_t g_xqh[SD], g_xql[SD];
__device__ uint16_t g_xvh[SD], g_xvl[SD];
__device__ uint16_t g_wqh[DMODEL*DMODEL], g_wql[DMODEL*DMODEL];
__device__ uint16_t g_wvh[DMODEL*DMODEL], g_wvl[DMODEL*DMODEL];
__device__ uint16_t g_Qh[SD], g_Ql[SD];
__device__ uint16_t g_Vh[SD], g_Vl[SD];
__device__ uint16_t g_Vth[SD];
__device__ float    g_S[SS];
__device__ uint16_t g_Ph[SS];

// ---------------------------------------------------------------------------
// helpers
// ---------------------------------------------------------------------------
__device__ __forceinline__ uint32_t smem_u32(const void* p) {
    uint32_t a;
    asm("{ .reg .u64 t; cvta.to.shared.u64 t, %1; cvt.u32.u64 %0, t; }" : "=r"(a) : "l"(p));
    return a;
}
__device__ __forceinline__ void cpasync16(uint32_t dst, const void* src) {
    asm volatile("{ .reg .u64 g; cvta.to.global.u64 g, %1; "
                 "cp.async.cg.shared.global [%0], [g], 16; }"
                 :: "r"(dst), "l"(src) : "memory");
}
#define CP_COMMIT() asm volatile("cp.async.commit_group;" ::: "memory")
#define CP_WAIT(n)  asm volatile("cp.async.wait_group %0;" :: "n"(n) : "memory")

#define LDSM4(d, addr) \
    asm volatile("ldmatrix.sync.aligned.m8n8.x4.shared.b16 {%0,%1,%2,%3}, [%4];" \
        : "=r"((d)[0]), "=r"((d)[1]), "=r"((d)[2]), "=r"((d)[3]) : "r"(addr))

template<int FP16>
__device__ __forceinline__ void mma16(float* d, const uint32_t* a,
                                      uint32_t b0, uint32_t b1v) {
    if constexpr (FP16) {
        asm volatile("mma.sync.aligned.m16n8k16.row.col.f32.f16.f16.f32 "
            "{%0,%1,%2,%3}, {%4,%5,%6,%7}, {%8,%9}, {%0,%1,%2,%3};"
            : "+f"(d[0]), "+f"(d[1]), "+f"(d[2]), "+f"(d[3])
            : "r"(a[0]), "r"(a[1]), "r"(a[2]), "r"(a[3]), "r"(b0), "r"(b1v));
    } else {
        asm volatile("mma.sync.aligned.m16n8k16.row.col.f32.bf16.bf16.f32 "
            "{%0,%1,%2,%3}, {%4,%5,%6,%7}, {%8,%9}, {%0,%1,%2,%3};"
            : "+f"(d[0]), "+f"(d[1]), "+f"(d[2]), "+f"(d[3])
            : "r"(a[0]), "r"(a[1]), "r"(a[2]), "r"(a[3]), "r"(b0), "r"(b1v));
    }
}

__device__ __forceinline__ void split2(float x, float y, uint32_t& hi, uint32_t& lo) {
    __nv_bfloat16 hx = __float2bfloat16(x), hy = __float2bfloat16(y);
    __nv_bfloat162 hp(hx, hy);
    hi = *reinterpret_cast<uint32_t*>(&hp);
    __nv_bfloat162 lp = __floats2bfloat162_rn(x - __bfloat162float(hx),
                                              y - __bfloat162float(hy));
    lo = *reinterpret_cast<uint32_t*>(&lp);
}

// ---------------------------------------------------------------------------
// 16-bit split NT GEMM:  C = scale * A·B^T (+ b1 + b2)
// TERMS=3: Ah*Bh + Ah*Bl + Al*Bh (bf16, 3 stages) ; TERMS=1: Ah*Bh (fp16, 6 stages)
// MODE bit0: fp32 C ; bit1: bf16 split Ch/Cl
// ---------------------------------------------------------------------------
template<int TERMS, int FP16, int MODE>
__global__ __launch_bounds__(THREADS, 1)
void gemm_nt(const uint16_t* __restrict__ Ah, const uint16_t* __restrict__ Al,
             const uint16_t* __restrict__ Bh, const uint16_t* __restrict__ Bl,
             float* __restrict__ C, uint16_t* __restrict__ Ch, uint16_t* __restrict__ Cl,
             int K, int ldc,
             const float* __restrict__ b1, const float* __restrict__ b2,
             float scale)
{
    constexpr int APL = (TERMS == 3) ? 2 : 1;
    constexpr int BPL = (TERMS >= 2) ? 2 : 1;
    constexpr uint32_t OFFAL = A_HALF;
    constexpr uint32_t OFFBH = (uint32_t)APL * A_HALF;
    constexpr uint32_t OFFBL = OFFBH + B_HALF;
    constexpr uint32_t STAGEB = (uint32_t)(APL * A_HALF + BPL * B_HALF);
    constexpr int NST = (TERMS == 3) ? 3 : 6;

    extern __shared__ char smem[];
    const uint32_t sbase = smem_u32(smem);
    const int tid = threadIdx.x, lane = tid & 31, w = tid >> 5;
    const int wm = w & 1, wn = w >> 1;

    const int m0 = blockIdx.y * BM;
    const int n0 = blockIdx.x * BN;

    const uint32_t offA = (uint32_t)((wm * 64 + ((lane >> 3) & 1) * 8 + (lane & 7)) * ROW_B
                                     + ((lane >> 4) & 1) * 16);
    const uint32_t offB = (uint32_t)((wn * 64 + ((lane >> 4) & 1) * 8 + (lane & 7)) * ROW_B
                                     + ((lane >> 3) & 1) * 16);

    float acc[4][8][4];
    #pragma unroll
    for (int i = 0; i < 4; ++i)
        #pragma unroll
        for (int j = 0; j < 8; ++j)
            #pragma unroll
            for (int q = 0; q < 4; ++q) acc[i][j][q] = 0.f;

    const int nc = K >> 5;

    auto issue = [&](int c, int s) {
        const uint32_t sb = sbase + (uint32_t)s * STAGEB;
        const int k0 = c * 32;
        #pragma unroll
        for (int i = 0; i < 2; ++i) {
            int idx = tid + i * 256;
            int row = idx >> 2, cc = idx & 3;
            const uint32_t d = sb + row * ROW_B + cc * 16;
            const long long g = (long long)(m0 + row) * K + k0 + cc * 8;
            cpasync16(d, Ah + g);
            if (TERMS == 3) cpasync16(d + OFFAL, Al + g);
        }
        #pragma unroll
        for (int i = 0; i < 4; ++i) {
            int idx = tid + i * 256;
            int row = idx >> 2, cc = idx & 3;
            const uint32_t d = sb + row * ROW_B + cc * 16;
            const long long g = (long long)(n0 + row) * K + k0 + cc * 8;
            cpasync16(d + OFFBH, Bh + g);
            if (TERMS >= 2) cpasync16(d + OFFBL, Bl + g);
        }
    };

    #pragma unroll
    for (int s = 0; s < NST - 1; ++s) { issue(s, s); CP_COMMIT(); }

    int st = 0;
    for (int c = 0; c < nc; ++c) {
        const int rem = nc - c - 1;
        if constexpr (NST == 3) {
            if (rem >= 1) { CP_WAIT(1); } else { CP_WAIT(0); }
        } else {
            if      (rem >= 4) { CP_WAIT(4); }
            else if (rem == 3) { CP_WAIT(3); }
            else if (rem == 2) { CP_WAIT(2); }
            else if (rem == 1) { CP_WAIT(1); }
            else               { CP_WAIT(0); }
        }
        __syncthreads();
        if (c + NST - 1 < nc) {
            int s = c + NST - 1;
            issue(s, s % NST); CP_COMMIT();
        }

        const uint32_t base = sbase + (uint32_t)st * STAGEB;
        #pragma unroll
        for (int kk2 = 0; kk2 < 2; ++kk2) {
            const uint32_t kb = kk2 * 32;
            uint32_t ah[4][4], bhf[4][4];
            #pragma unroll
            for (int mi = 0; mi < 4; ++mi) LDSM4(ah[mi], base + offA + mi * (16 * ROW_B) + kb);
            #pragma unroll
            for (int nt = 0; nt < 4; ++nt) LDSM4(bhf[nt], base + OFFBH + offB + nt * (16 * ROW_B) + kb);
            #pragma unroll
            for (int mi = 0; mi < 4; ++mi)
                #pragma unroll
                for (int nt = 0; nt < 4; ++nt)
                    #pragma unroll
                    for (int nh = 0; nh < 2; ++nh)
                        mma16<FP16>(acc[mi][nt * 2 + nh], ah[mi], bhf[nt][nh * 2], bhf[nt][nh * 2 + 1]);
            if constexpr (TERMS >= 2) {
                uint32_t blf[4][4];
                #pragma unroll
                for (int nt = 0; nt < 4; ++nt) LDSM4(blf[nt], base + OFFBL + offB + nt * (16 * ROW_B) + kb);
                #pragma unroll
                for (int mi = 0; mi < 4; ++mi)
                    #pragma unroll
                    for (int nt = 0; nt < 4; ++nt)
                        #pragma unroll
                        for (int nh = 0; nh < 2; ++nh)
                            mma16<FP16>(acc[mi][nt * 2 + nh], ah[mi], blf[nt][nh * 2], blf[nt][nh * 2 + 1]);
            }
            if constexpr (TERMS == 3) {
                uint32_t alf[4][4];
                #pragma unroll
                for (int mi = 0; mi < 4; ++mi) LDSM4(alf[mi], base + OFFAL + offA + mi * (16 * ROW_B) + kb);
                #pragma unroll
                for (int mi = 0; mi < 4; ++mi)
                    #pragma unroll
                    for (int nt = 0; nt < 4; ++nt)
                        #pragma unroll
                        for (int nh = 0; nh < 2; ++nh)
                            mma16<FP16>(acc[mi][nt * 2 + nh], alf[mi], bhf[nt][nh * 2], bhf[nt][nh * 2 + 1]);
            }
        }

        if (++st == NST) st = 0;
    }

    const int gid = lane >> 2, tig = lane & 3;
    #pragma unroll
    for (int mi = 0; mi < 4; ++mi) {
        const int row = m0 + wm * 64 + mi * 16 + gid;
        #pragma unroll
        for (int ni = 0; ni < 8; ++ni) {
            const int col = n0 + wn * 64 + ni * 8 + tig * 2;
            float bb0 = 0.f, bb1 = 0.f;
            if (b1) { bb0 += b1[col]; bb1 += b1[col + 1]; }
            if (b2) { bb0 += b2[col]; bb1 += b2[col + 1]; }
            float2 o0, o1;
            o0.x = acc[mi][ni][0] * scale + bb0;
            o0.y = acc[mi][ni][1] * scale + bb1;
            o1.x = acc[mi][ni][2] * scale + bb0;
            o1.y = acc[mi][ni][3] * scale + bb1;
            const long long i0 = (long long)row * ldc + col;
            const long long i1 = i0 + 8LL * ldc;
            if constexpr (MODE & 1) {
                *(float2*)(C + i0) = o0;
                *(float2*)(C + i1) = o1;
            }
            if constexpr (MODE & 2) {
                uint32_t h, l;
                split2(o0.x, o0.y, h, l);
                *(uint32_t*)(Ch + i0) = h; *(uint32_t*)(Cl + i0) = l;
                split2(o1.x, o1.y, h, l);
                *(uint32_t*)(Ch + i1) = h; *(uint32_t*)(Cl + i1) = l;
            }
        }
    }
}

// ---------------------------------------------------------------------------
// fp32 -> bf16 hi/lo split
// ---------------------------------------------------------------------------
__global__ __launch_bounds__(256)
void split_f32(const float4* __restrict__ in, uint2* __restrict__ hi,
               uint2* __restrict__ lo, int n4)
{
    int i = blockIdx.x * 256 + threadIdx.x;
    if (i >= n4) return;
    float4 v = in[i];
    uint32_t h0, l0, h1, l1;
    split2(v.x, v.y, h0, l0);
    split2(v.z, v.w, h1, l1);
    hi[i] = make_uint2(h0, h1);
    lo[i] = make_uint2(l0, l1);
}

// ---------------------------------------------------------------------------
// Per-batch V transpose from bf16 hi/lo planes -> fp16 (pointers pre-offset)
// ---------------------------------------------------------------------------
__global__ __launch_bounds__(256)
void transpose_v16(const uint16_t* __restrict__ Hh, const uint16_t* __restrict__ Hl,
                   uint16_t* __restrict__ T)
{
    __shared__ float t[32][33];
    const int s0 = blockIdx.x * 32;
    const int d0 = blockIdx.y * 32;
    const int x = threadIdx.x, y = threadIdx.y;
    #pragma unroll
    for (int i = 0; i < 32; i += 8) {
        const long long g = (long long)(s0 + y + i) * DMODEL + d0 + x;
        __nv_bfloat16 hb = *reinterpret_cast<const __nv_bfloat16*>(Hh + g);
        __nv_bfloat16 lb = *reinterpret_cast<const __nv_bfloat16*>(Hl + g);
        t[y + i][x] = __bfloat162float(hb) + __bfloat162float(lb);
    }
    __syncthreads();
    #pragma unroll
    for (int i = 0; i < 32; i += 8) {
        __half h = __float2half_rn(t[x][y + i]);
        T[(long long)(d0 + y + i) * SEQ + s0 + x] = *reinterpret_cast<uint16_t*>(&h);
    }
}

// ---------------------------------------------------------------------------
// Row softmax: fp32 in, fp16 out
// ---------------------------------------------------------------------------
__global__ __launch_bounds__(512)
void softmax_rows(const float* __restrict__ S, uint16_t* __restrict__ Ph)
{
    const float* p = S + (long long)blockIdx.x * SEQ;
    const int tid = threadIdx.x;

    float4 a = ((const float4*)p)[tid];
    float4 b = ((const float4*)p)[tid + 512];

    __shared__ float sred[16];
    __shared__ float sval;

    float m = fmaxf(fmaxf(fmaxf(a.x, a.y), fmaxf(a.z, a.w)),
                    fmaxf(fmaxf(b.x, b.y), fmaxf(b.z, b.w)));
    #pragma unroll
    for (int o = 16; o > 0; o >>= 1) m = fmaxf(m, __shfl_xor_sync(0xffffffffu, m, o));
    if ((tid & 31) == 0) sred[tid >> 5] = m;
    __syncthreads();
    if (tid < 32) {
        float x = (tid < 16) ? sred[tid] : __int_as_float(0xff800000);
        #pragma unroll
        for (int o = 8; o > 0; o >>= 1) x = fmaxf(x, __shfl_xor_sync(0xffffffffu, x, o));
        if (tid == 0) sval = x;
    }
    __syncthreads();
    const float rmax = sval;
    __syncthreads();

    a.x = expf(a.x - rmax); a.y = expf(a.y - rmax);
    a.z = expf(a.z - rmax); a.w = expf(a.w - rmax);
    b.x = expf(b.x - rmax); b.y = expf(b.y - rmax);
    b.z = expf(b.z - rmax); b.w = expf(b.w - rmax);

    float s = (a.x + a.y) + (a.z + a.w) + (b.x + b.y) + (b.z + b.w);
    #pragma unroll
    for (int o = 16; o > 0; o >>= 1) s += __shfl_xor_sync(0xffffffffu, s, o);
    if ((tid & 31) == 0) sred[tid >> 5] = s;
    __syncthreads();
    if (tid < 32) {
        float x = (tid < 16) ? sred[tid] : 0.f;
        #pragma unroll
        for (int o = 8; o > 0; o >>= 1) x += __shfl_xor_sync(0xffffffffu, x, o);
        if (tid == 0) sval = x;
    }
    __syncthreads();
    const float inv = 1.0f / sval;

    __half2 p0 = __floats2half2_rn(a.x * inv, a.y * inv);
    __half2 p1 = __floats2half2_rn(a.z * inv, a.w * inv);
    __half2 p2 = __floats2half2_rn(b.x * inv, b.y * inv);
    __half2 p3 = __floats2half2_rn(b.z * inv, b.w * inv);

    const long long rb = (long long)blockIdx.x * (SEQ / 4);
    ((uint2*)Ph)[rb + tid]       = make_uint2(*reinterpret_cast<uint32_t*>(&p0),
                                              *reinterpret_cast<uint32_t*>(&p1));
    ((uint2*)Ph)[rb + 512 + tid] = make_uint2(*reinterpret_cast<uint32_t*>(&p2),
                                              *reinterpret_cast<uint32_t*>(&p3));
}

// ---------------------------------------------------------------------------
// Launcher — per-batch chains end-to-end on 4 streams; no global joins.
// Only cross-stream deps: the 4 split kernels (evXQ/evXV).
// ---------------------------------------------------------------------------
extern "C" void kernel_launch(void* const* d_in, const int* in_sizes, int n_in,
                              void* d_out, int out_size)
{
    const float* query = (const float*)d_in[0];
    const float* value = (const float*)d_in[1];
    const float* Wq    = (const float*)d_in[2];
    const float* bq    = (const float*)d_in[3];
    const float* qkb   = (const float*)d_in[4];
    const float* Wv    = (const float*)d_in[5];
    const float* bv    = (const float*)d_in[6];
    float* out = (float*)d_out;

    uint16_t *xqh, *xql, *xvh, *xvl, *wqh, *wql, *wvh, *wvl;
    uint16_t *Qh, *Ql, *Vh, *Vl, *Vth, *Ph;
    float *Sc;
    cudaGetSymbolAddress((void**)&xqh, g_xqh); cudaGetSymbolAddress((void**)&xql, g_xql);
    cudaGetSymbolAddress((void**)&xvh, g_xvh); cudaGetSymbolAddress((void**)&xvl, g_xvl);
    cudaGetSymbolAddress((void**)&wqh, g_wqh); cudaGetSymbolAddress((void**)&wql, g_wql);
    cudaGetSymbolAddress((void**)&wvh, g_wvh); cudaGetSymbolAddress((void**)&wvl, g_wvl);
    cudaGetSymbolAddress((void**)&Qh,  g_Qh);  cudaGetSymbolAddress((void**)&Ql,  g_Ql);
    cudaGetSymbolAddress((void**)&Vh,  g_Vh);  cudaGetSymbolAddress((void**)&Vl,  g_Vl);
    cudaGetSymbolAddress((void**)&Vth, g_Vth);
    cudaGetSymbolAddress((void**)&Sc,  g_S);
    cudaGetSymbolAddress((void**)&Ph,  g_Ph);

    static bool init_done = false;
    static cudaStream_t st[3];
    static cudaEvent_t evEntry, evXQ, evXV, evB[3];
    if (!init_done) {
        cudaFuncSetAttribute(gemm_nt<3,0,1>, cudaFuncAttributeMaxDynamicSharedMemorySize, SMEM_DYN);
        cudaFuncSetAttribute(gemm_nt<3,0,2>, cudaFuncAttributeMaxDynamicSharedMemorySize, SMEM_DYN);
        cudaFuncSetAttribute(gemm_nt<1,1,1>, cudaFuncAttributeMaxDynamicSharedMemorySize, SMEM_DYN);
        for (int i = 0; i < 3; ++i) cudaStreamCreateWithFlags(&st[i], cudaStreamNonBlocking);
        cudaEventCreateWithFlags(&evEntry, cudaEventDisableTiming);
        cudaEventCreateWithFlags(&evXQ,    cudaEventDisableTiming);
        cudaEventCreateWithFlags(&evXV,    cudaEventDisableTiming);
        for (int i = 0; i < 3; ++i) cudaEventCreateWithFlags(&evB[i], cudaEventDisableTiming);
        init_done = true;
    }

    const int S = SEQ, D = DMODEL, B = BATCH;
    const long long sd = (long long)S * D;
    const long long ss = (long long)S * S;

    // fork all worker streams from origin
    cudaEventRecord(evEntry, 0);
    for (int i = 0; i < 3; ++i) cudaStreamWaitEvent(st[i], evEntry, 0);

    // splits: q/Wq on origin, v/Wv on st[0]
    split_f32<<<(B*S*D/4 + 255)/256, 256>>>((const float4*)query, (uint2*)xqh, (uint2*)xql, B*S*D/4);
    split_f32<<<(D*D/4 + 255)/256, 256>>>((const float4*)Wq, (uint2*)wqh, (uint2*)wql, D*D/4);
    cudaEventRecord(evXQ, 0);
    split_f32<<<(B*S*D/4 + 255)/256, 256, 0, st[0]>>>((const float4*)value, (uint2*)xvh, (uint2*)xvl, B*S*D/4);
    split_f32<<<(D*D/4 + 255)/256, 256, 0, st[0]>>>((const float4*)Wv, (uint2*)wvh, (uint2*)wvl, D*D/4);
    cudaEventRecord(evXV, 0 ? 0 : st[0]);

    // per-batch end-to-end chains
    dim3 gp(D / BN, S / BM, 1);       // per-batch projection: 4 x 32 CTAs
    dim3 gs(S / BN, S / BM, 1);       // per-batch scores
    dim3 go(D / BN, S / BM, 1);       // per-batch PV
    dim3 gt(S / 32, D / 32, 1);       // per-batch transpose

    for (int b = 0; b < B; ++b) {
        cudaStream_t sb = (b == 0) ? (cudaStream_t)0 : st[b - 1];
        // deps on the split prefix (skip redundant same-stream waits)
        if (b != 0) cudaStreamWaitEvent(sb, evXQ, 0);    // origin has program order
        if (b != 1) cudaStreamWaitEvent(sb, evXV, 0);    // st[0] has program order

        // projQ_b : Q[b] = query[b]·Wq^T + bq + qk_b   (bf16 split out)
        gemm_nt<3,0,2><<<gp, THREADS, SMEM_DYN, sb>>>(
            xqh + b * sd, xql + b * sd, wqh, wql,
            nullptr, Qh + b * sd, Ql + b * sd, D, D,
            bq, qkb, 1.0f);
        // projV_b : V[b] = value[b]·Wv^T + bv          (bf16 split out)
        gemm_nt<3,0,2><<<gp, THREADS, SMEM_DYN, sb>>>(
            xvh + b * sd, xvl + b * sd, wvh, wvl,
            nullptr, Vh + b * sd, Vl + b * sd, D, D,
            bv, nullptr, 1.0f);
        // transpose_b : Vth[b] (fp16)
        transpose_v16<<<gt, dim3(32, 8), 0, sb>>>(Vh + b * sd, Vl + b * sd, Vth + b * sd);
        // scores_b : Sc[b] = Q[b]·V[b]^T / 8           (fp32 out)
        gemm_nt<3,0,1><<<gs, THREADS, SMEM_DYN, sb>>>(
            Qh + b * sd, Ql + b * sd, Vh + b * sd, Vl + b * sd,
            Sc + b * ss, nullptr, nullptr, D, S,
            nullptr, nullptr, 0.125f);
        // softmax_b -> Ph[b] (fp16)
        softmax_rows<<<S, 512, 0, sb>>>(Sc + b * ss, Ph + b * ss);
        // PV_b : out[b] = P[b]·Vth[b]^T
        gemm_nt<1,1,1><<<go, THREADS, SMEM_DYN, sb>>>(
            Ph + b * ss, nullptr, Vth + b * sd, nullptr,
            out + b * sd, nullptr, nullptr, S, D,
            nullptr, nullptr, 1.0f);

        if (b > 0) cudaEventRecord(evB[b - 1], sb);
    }
    for (int i = 0; i < 3; ++i) cudaStreamWaitEvent(0, evB[i], 0);
}